// round 10
// baseline (speedup 1.0000x reference)
#include <cuda_runtime.h>
#include <cuda_fp16.h>

#define RES     256
#define CHOUT   16
#define NCH     128          // CH*RR phasor channels per plane
#define NPTS    262144
#define NBIN    65536
#define PI_F    3.14159265358979323846f

// Scratch (device globals: allocation-free rule)
__device__ float2   g_mid[128 * 256 * NCH];        // [ky<128][x][ch] fp32, 33.5 MB
__device__ __half   g_feat[RES * RES * 2 * NCH];   // [y][x][256ch] fp16 unnormalized
__device__ unsigned g_hist[3][NBIN];
__device__ unsigned g_ofs [3][NBIN];
__device__ int      g_pid [3][NPTS];               // texel-sorted point ids per plane

__device__ __forceinline__ float2 cadd(float2 a, float2 b) { return make_float2(a.x + b.x, a.y + b.y); }
__device__ __forceinline__ float2 csub(float2 a, float2 b) { return make_float2(a.x - b.x, a.y - b.y); }
__device__ __forceinline__ float2 cmul(float2 a, float2 b) {
    return make_float2(fmaf(a.x, b.x, -a.y * b.y), fmaf(a.x, b.y, a.y * b.x));
}
__device__ __forceinline__ float2 muli(float2 a) { return make_float2(-a.y, a.x); }

// ===========================================================================
// Register DFT-16 (inverse, +i), radix-4 x radix-4, natural-order output.
// (unchanged from R9)
// ===========================================================================
__device__ __forceinline__ float2 w16m(int k) {
    const float C1 = 0.9238795325112867f, S1 = 0.3826834323650898f;
    const float C2 = 0.7071067811865476f;
    switch (k) {
        case 0:  return make_float2( 1.f, 0.f);
        case 1:  return make_float2( C1,  S1);
        case 2:  return make_float2( C2,  C2);
        case 3:  return make_float2( S1,  C1);
        case 4:  return make_float2( 0.f, 1.f);
        case 6:  return make_float2(-C2,  C2);
        default: return make_float2(-C1, -S1);     // case 9
    }
}

__device__ __forceinline__ void dft4i(float2& x0, float2& x1, float2& x2, float2& x3) {
    float2 a = cadd(x0, x2), b = csub(x0, x2);
    float2 c = cadd(x1, x3), d = muli(csub(x1, x3));
    x0 = cadd(a, c); x1 = cadd(b, d); x2 = csub(a, c); x3 = csub(b, d);
}

__device__ __forceinline__ void dft16_tail(float2 d[16], float2 out[16]) {
#pragma unroll
    for (int m = 0; m < 4; m++) {
        float2 e0 = d[0 + 4 * m];
        float2 e1 = cmul(d[1 + 4 * m], w16m(1 * m));
        float2 e2 = cmul(d[2 + 4 * m], w16m(2 * m));
        float2 e3 = cmul(d[3 + 4 * m], w16m(3 * m));
        float2 A = cadd(e0, e2), B = csub(e0, e2);
        float2 C = cadd(e1, e3), D = muli(csub(e1, e3));
        out[m]      = cadd(A, C);
        out[m + 4]  = cadd(B, D);
        out[m + 8]  = csub(A, C);
        out[m + 12] = csub(B, D);
    }
}

__device__ __forceinline__ void dft16_full(float2 x[16], float2 out[16]) {
#pragma unroll
    for (int a = 0; a < 4; a++) dft4i(x[a], x[a + 4], x[a + 8], x[a + 12]);
    dft16_tail(x, out);
}

__device__ __forceinline__ void dft16_half(const float2 x[8], float2 out[16]) {
    float2 d[16];
#pragma unroll
    for (int a = 0; a < 4; a++) {
        float2 u = x[a], v = x[a + 4];
        float2 iv = muli(v);
        d[a]      = cadd(u, v);
        d[a + 4]  = cadd(u, iv);
        d[a + 8]  = csub(u, v);
        d[a + 12] = csub(u, iv);
    }
    dft16_tail(d, out);
}

// ===========================================================================
// FFT kernels (unchanged from R9): 16 threads per 256-pt IFFT.
// ===========================================================================
__global__ void __launch_bounds__(256) kfftx(const float* __restrict__ P) {
    __shared__ float2 sbuf[4352];
    int tid = threadIdx.x, g = blockIdx.x, ky = blockIdx.y;
    int f = tid >> 4, n1 = tid & 15;
    int ch = g * 16 + f;

    const float2* row = (const float2*)P + ((size_t)ch * 256 + ky) * 256;
    float2 x[8];
#pragma unroll
    for (int j = 0; j < 8; j++) x[j] = row[n1 + 16 * j];

    float2 A[16];
    dft16_half(x, A);

    float sn, cs;
    sincosf(PI_F * (float)n1 / 128.f, &sn, &cs);
    float2 base = make_float2(cs, sn), w = make_float2(1.f, 0.f);
    float2* tp = sbuf + f * 272 + n1;
#pragma unroll
    for (int k1 = 0; k1 < 16; k1++) {
        tp[k1 * 17] = cmul(A[k1], w);
        w = cmul(w, base);
    }
    __syncthreads();

    float2 c[16];
    const float2* rp = sbuf + f * 272 + n1 * 17;
#pragma unroll
    for (int i = 0; i < 16; i++) c[i] = rp[i];
    __syncthreads();

    float2 X[16];
    dft16_full(c, X);

#pragma unroll
    for (int k2 = 0; k2 < 16; k2++) sbuf[(n1 + 16 * k2) * 17 + f] = X[k2];
    __syncthreads();

    float2* dst = g_mid + (size_t)ky * 256 * 128 + g * 16;
#pragma unroll
    for (int k = 0; k < 16; k++) {
        int idx = tid + k * 256;
        int xx = idx >> 4, ff = idx & 15;
        dst[(size_t)xx * 128 + ff] = sbuf[xx * 17 + ff];
    }
}

__global__ void __launch_bounds__(256) kffty() {
    __shared__ float2 sbuf[4352];
    int tid = threadIdx.x, g = blockIdx.x, xcol = blockIdx.y;
    int f = tid >> 4, n1 = tid & 15;

    const float2* src = g_mid + (size_t)xcol * 128 + g * 16;
#pragma unroll
    for (int k = 0; k < 8; k++) {
        int idx = tid + k * 256;
        int kyi = idx >> 4, ff = idx & 15;
        sbuf[kyi * 17 + ff] = src[(size_t)kyi * 256 * 128 + ff];
    }
    __syncthreads();

    float2 x[8];
#pragma unroll
    for (int j = 0; j < 8; j++) x[j] = sbuf[(n1 + 16 * j) * 17 + f];
    __syncthreads();

    float2 A[16];
    dft16_half(x, A);

    float sn, cs;
    sincosf(PI_F * (float)n1 / 128.f, &sn, &cs);
    float2 base = make_float2(cs, sn), w = make_float2(1.f, 0.f);
    float2* tp = sbuf + f * 272 + n1;
#pragma unroll
    for (int k1 = 0; k1 < 16; k1++) {
        tp[k1 * 17] = cmul(A[k1], w);
        w = cmul(w, base);
    }
    __syncthreads();

    float2 c[16];
    const float2* rp = sbuf + f * 272 + n1 * 17;
#pragma unroll
    for (int i = 0; i < 16; i++) c[i] = rp[i];
    __syncthreads();

    float2 X[16];
    dft16_full(c, X);

#pragma unroll
    for (int k2 = 0; k2 < 16; k2++) sbuf[(n1 + 16 * k2) * 17 + f] = X[k2];
    __syncthreads();

    __half2* dst = (__half2*)g_feat + (size_t)xcol * 128 + g * 16;
#pragma unroll
    for (int k = 0; k < 16; k++) {
        int idx = tid + k * 256;
        int y = idx >> 4, ff = idx & 15;
        float2 v = sbuf[y * 17 + ff];
        dst[(size_t)y * 256 * 128 + ff] = __floats2half2_rn(v.x, v.y);
    }
}

// ===========================================================================
// Counting sort of point ids by (y0,x0) texel bin, per plane (exact reorder).
// Slim R7 version (validated correct there): id-only scatter, fused scan.
// ===========================================================================
__device__ __forceinline__ int binkey(float gx, float gy) {
    float xx = (gx + 1.f) * 127.5f;
    float yy = (gy + 1.f) * 127.5f;
    int x0 = min(max(__float2int_rd(xx), 0), 255);
    int y0 = min(max(__float2int_rd(yy), 0), 255);
    return (y0 << 8) | x0;
}
__device__ __forceinline__ void plane_coords(int p, float i0, float i1, float i2,
                                             float& gx, float& gy, float& s) {
    if (p == 0)      { gx = i1; gy = i2; s = i0; }
    else if (p == 1) { gx = i0; gy = i2; s = i1; }
    else             { gx = i0; gy = i1; s = i2; }
}

__global__ void kzero() {
    int i = blockIdx.x * blockDim.x + threadIdx.x;
    if (i < 3 * NBIN) ((unsigned*)g_hist)[i] = 0;
}

__global__ void khist(const float* __restrict__ inputs) {
    int pt = blockIdx.x * blockDim.x + threadIdx.x;
    float i0 = inputs[pt * 3 + 0];
    float i1 = inputs[pt * 3 + 1];
    float i2 = inputs[pt * 3 + 2];
#pragma unroll
    for (int p = 0; p < 3; p++) {
        float gx, gy, s;
        plane_coords(p, i0, i1, i2, gx, gy, s);
        atomicAdd(&g_hist[p][binkey(gx, gy)], 1u);
    }
}

__global__ void __launch_bounds__(1024) kscan() {
    int p = blockIdx.x, t = threadIdx.x;
    int base = t * 64;
    unsigned s = 0;
#pragma unroll 8
    for (int i = 0; i < 64; i++) s += g_hist[p][base + i];

    __shared__ unsigned wsum[32];
    int lane = t & 31, w = t >> 5;
    unsigned inc = s;
#pragma unroll
    for (int d = 1; d < 32; d <<= 1) {
        unsigned n = __shfl_up_sync(0xffffffffu, inc, d);
        if (lane >= d) inc += n;
    }
    if (lane == 31) wsum[w] = inc;
    __syncthreads();
    if (w == 0) {
        unsigned v = wsum[lane];
#pragma unroll
        for (int d = 1; d < 32; d <<= 1) {
            unsigned n = __shfl_up_sync(0xffffffffu, v, d);
            if (lane >= d) v += n;
        }
        wsum[lane] = v;
    }
    __syncthreads();
    unsigned run = inc - s + ((w == 0) ? 0u : wsum[w - 1]);
    for (int i = 0; i < 64; i++) {
        unsigned h = g_hist[p][base + i];
        g_ofs[p][base + i] = run;
        run += h;
    }
}

__global__ void kscatter(const float* __restrict__ inputs) {
    int pt = blockIdx.x * blockDim.x + threadIdx.x;
    float i0 = inputs[pt * 3 + 0];
    float i1 = inputs[pt * 3 + 1];
    float i2 = inputs[pt * 3 + 2];
#pragma unroll
    for (int p = 0; p < 3; p++) {
        float gx, gy, s;
        plane_coords(p, i0, i1, i2, gx, gy, s);
        unsigned pos = atomicAdd(&g_ofs[p][binkey(gx, gy)], 1u);
        g_pid[p][pos] = pt;
    }
}

// ===========================================================================
// Sampler (R9 hot path, unchanged math): one warp per SORTED point.
// Deltas vs R9: pid indirection (1 broadcast LDG) + out[pid] scatter.
// Sorted order -> consecutive warps/blocks share texels -> L1 reuse.
// ===========================================================================
__global__ void __launch_bounds__(256)
ksample(int p, const float* __restrict__ inputs, float* __restrict__ out, int accum) {
    int wl = (blockIdx.x * blockDim.x + threadIdx.x) >> 5;
    int lane = threadIdx.x & 31;
    if (wl >= NPTS) return;

    int pid = __ldg(&g_pid[p][wl]);
    float i0 = __ldg(inputs + pid * 3 + 0);
    float i1 = __ldg(inputs + pid * 3 + 1);
    float i2 = __ldg(inputs + pid * 3 + 2);
    float gx, gy, ic;
    plane_coords(p, i0, i1, i2, gx, gy, ic);

    float xx = (gx + 1.f) * 127.5f;
    float yy = (gy + 1.f) * 127.5f;
    float xf = floorf(xx), yf = floorf(yy);
    float wx = xx - xf, wy = yy - yf;
    int x0 = min(max((int)xf, 0), 255);
    int x1 = min(x0 + 1, 255);
    int y0 = min(max((int)yf, 0), 255);
    int y1 = min(y0 + 1, 255);
    __half2 w00 = __float2half2_rn((1.f - wx) * (1.f - wy));
    __half2 w01 = __float2half2_rn(wx * (1.f - wy));
    __half2 w10 = __float2half2_rn((1.f - wx) * wy);
    __half2 w11 = __float2half2_rn(wx * wy);

    int co = lane << 3;
    uint4 u00 = __ldg((const uint4*)(g_feat + ((((y0 << 8) + x0) << 8) + co)));
    uint4 u01 = __ldg((const uint4*)(g_feat + ((((y0 << 8) + x1) << 8) + co)));
    uint4 u10 = __ldg((const uint4*)(g_feat + ((((y1 << 8) + x0) << 8) + co)));
    uint4 u11 = __ldg((const uint4*)(g_feat + ((((y1 << 8) + x1) << 8) + co)));
    const __half2* h00 = (const __half2*)&u00;
    const __half2* h01 = (const __half2*)&u01;
    const __half2* h10 = (const __half2*)&u10;
    const __half2* h11 = (const __half2*)&u11;

    float F[8];
#pragma unroll
    for (int k = 0; k < 4; k++) {
        __half2 a = __hfma2(w01, h01[k], __hmul2(w00, h00[k]));
        __half2 b = __hfma2(w11, h11[k], __hmul2(w10, h10[k]));
        float2 fa = __half22float2(a);
        float2 fb = __half22float2(b);
        F[2 * k]     = fa.x + fb.x;
        F[2 * k + 1] = fa.y + fb.y;
    }

    float s = (ic + 1.f) * 127.5f;
    float a = s * (PI_F / 128.f);
    bool re = (lane < 16);
    float sa  = re ? a : -a;
    float off = re ? (PI_F * 0.5f) : 0.f;
    float val = re ? F[0] : 0.f;
#pragma unroll
    for (int r = 1; r < 8; r++) {
        float th = fmaf((float)((1 << r) - 1), sa, off);
        val = fmaf(F[r], __sinf(th), val);
    }
    val += __shfl_down_sync(0xffffffffu, val, 16);
    if (lane < 16) {
        float v = val * (1.f / 65536.f);
        float* o = out + pid * CHOUT + lane;
        if (accum) *o += v; else *o = v;
    }
}

// ---------------------------------------------------------------------------
extern "C" void kernel_launch(void* const* d_in, const int* in_sizes, int n_in,
                              void* d_out, int out_size) {
    const float* inp = (const float*)d_in[3];
    float* out = (float*)d_out;

    kzero<<<(3 * NBIN + 1023) / 1024, 1024>>>();
    khist<<<NPTS / 256, 256>>>(inp);
    kscan<<<3, 1024>>>();
    kscatter<<<NPTS / 256, 256>>>(inp);

    for (int p = 0; p < 3; p++) {
        const float* P = (const float*)d_in[p];
        kfftx<<<dim3(NCH / 16, 128), 256>>>(P);
        kffty<<<dim3(NCH / 16, 256), 256>>>();
        ksample<<<NPTS / 8, 256>>>(p, inp, out, p > 0);
    }
}

// round 11
// speedup vs baseline: 1.7175x; 1.7175x over previous
#include <cuda_runtime.h>
#include <cuda_fp16.h>

#define RES     256
#define CHOUT   16
#define NCH     128          // CH*RR phasor channels per plane
#define NPTS    262144
#define PI_F    3.14159265358979323846f

// Scratch (device globals: allocation-free rule)
__device__ __half2 g_mid[128 * 256 * NCH];         // [ky<128][x][ch] complex fp16, 16.7 MB
__device__ __half  g_feat[RES * RES * 2 * NCH];    // [y][x][256ch] fp16 unnormalized

__device__ __forceinline__ float2 cadd(float2 a, float2 b) { return make_float2(a.x + b.x, a.y + b.y); }
__device__ __forceinline__ float2 csub(float2 a, float2 b) { return make_float2(a.x - b.x, a.y - b.y); }
__device__ __forceinline__ float2 cmul(float2 a, float2 b) {
    return make_float2(fmaf(a.x, b.x, -a.y * b.y), fmaf(a.x, b.y, a.y * b.x));
}
__device__ __forceinline__ float2 muli(float2 a) { return make_float2(-a.y, a.x); }

// ===========================================================================
// Register DFT-16 (inverse, +i), radix-4 x radix-4, natural-order output.
// (unchanged from R9)
// ===========================================================================
__device__ __forceinline__ float2 w16m(int k) {
    const float C1 = 0.9238795325112867f, S1 = 0.3826834323650898f;
    const float C2 = 0.7071067811865476f;
    switch (k) {
        case 0:  return make_float2( 1.f, 0.f);
        case 1:  return make_float2( C1,  S1);
        case 2:  return make_float2( C2,  C2);
        case 3:  return make_float2( S1,  C1);
        case 4:  return make_float2( 0.f, 1.f);
        case 6:  return make_float2(-C2,  C2);
        default: return make_float2(-C1, -S1);     // case 9
    }
}

__device__ __forceinline__ void dft4i(float2& x0, float2& x1, float2& x2, float2& x3) {
    float2 a = cadd(x0, x2), b = csub(x0, x2);
    float2 c = cadd(x1, x3), d = muli(csub(x1, x3));
    x0 = cadd(a, c); x1 = cadd(b, d); x2 = csub(a, c); x3 = csub(b, d);
}

__device__ __forceinline__ void dft16_tail(float2 d[16], float2 out[16]) {
#pragma unroll
    for (int m = 0; m < 4; m++) {
        float2 e0 = d[0 + 4 * m];
        float2 e1 = cmul(d[1 + 4 * m], w16m(1 * m));
        float2 e2 = cmul(d[2 + 4 * m], w16m(2 * m));
        float2 e3 = cmul(d[3 + 4 * m], w16m(3 * m));
        float2 A = cadd(e0, e2), B = csub(e0, e2);
        float2 C = cadd(e1, e3), D = muli(csub(e1, e3));
        out[m]      = cadd(A, C);
        out[m + 4]  = cadd(B, D);
        out[m + 8]  = csub(A, C);
        out[m + 12] = csub(B, D);
    }
}

__device__ __forceinline__ void dft16_full(float2 x[16], float2 out[16]) {
#pragma unroll
    for (int a = 0; a < 4; a++) dft4i(x[a], x[a + 4], x[a + 8], x[a + 12]);
    dft16_tail(x, out);
}

__device__ __forceinline__ void dft16_half(const float2 x[8], float2 out[16]) {
    float2 d[16];
#pragma unroll
    for (int a = 0; a < 4; a++) {
        float2 u = x[a], v = x[a + 4];
        float2 iv = muli(v);
        d[a]      = cadd(u, v);
        d[a + 4]  = cadd(u, iv);
        d[a + 8]  = csub(u, v);
        d[a + 12] = csub(u, iv);
    }
    dft16_tail(d, out);
}

// ===========================================================================
// FFT kernels (R9 structure): 16 threads per 256-pt IFFT, 16 FFTs/block.
// Only change: g_mid is complex fp16 (halves intermediate traffic).
// ===========================================================================
__global__ void __launch_bounds__(256) kfftx(const float* __restrict__ P) {
    __shared__ float2 sbuf[4352];                  // 34 KB multi-purpose
    int tid = threadIdx.x, g = blockIdx.x, ky = blockIdx.y;
    int f = tid >> 4, n1 = tid & 15;
    int ch = g * 16 + f;

    const float2* row = (const float2*)P + ((size_t)ch * 256 + ky) * 256;
    float2 x[8];
#pragma unroll
    for (int j = 0; j < 8; j++) x[j] = row[n1 + 16 * j];   // coalesced 128B

    float2 A[16];
    dft16_half(x, A);

    // twiddle W256^(n1*k1) (register recurrence) + transpose store [f][k1][n1]
    float sn, cs;
    sincosf(PI_F * (float)n1 / 128.f, &sn, &cs);   // exp(+i*2pi*n1/256)
    float2 base = make_float2(cs, sn), w = make_float2(1.f, 0.f);
    float2* tp = sbuf + f * 272 + n1;
#pragma unroll
    for (int k1 = 0; k1 < 16; k1++) {
        tp[k1 * 17] = cmul(A[k1], w);
        w = cmul(w, base);
    }
    __syncthreads();

    float2 c[16];
    const float2* rp = sbuf + f * 272 + n1 * 17;   // role: this thread = k1
#pragma unroll
    for (int i = 0; i < 16; i++) c[i] = rp[i];
    __syncthreads();

    float2 X[16];
    dft16_full(c, X);                              // X[k2] -> x-pos n1 + 16*k2

#pragma unroll
    for (int k2 = 0; k2 < 16; k2++) sbuf[(n1 + 16 * k2) * 17 + f] = X[k2];
    __syncthreads();

    __half2* dst = g_mid + (size_t)ky * 256 * 128 + g * 16;
#pragma unroll
    for (int k = 0; k < 16; k++) {
        int idx = tid + k * 256;                   // 4096 = 256 x * 16 ch
        int xx = idx >> 4, ff = idx & 15;
        float2 v = sbuf[xx * 17 + ff];
        dst[(size_t)xx * 128 + ff] = __floats2half2_rn(v.x, v.y);  // 64B chunks
    }
}

__global__ void __launch_bounds__(256) kffty() {
    __shared__ float2 sbuf[4352];
    int tid = threadIdx.x, g = blockIdx.x, xcol = blockIdx.y;
    int f = tid >> 4, n1 = tid & 15;

    // Stage input column: g_mid[ky][xcol][g*16+ff] -> sbuf[ky][ff] (fp32)
    const __half2* src = g_mid + (size_t)xcol * 128 + g * 16;
#pragma unroll
    for (int k = 0; k < 8; k++) {
        int idx = tid + k * 256;                   // 2048 = 128 ky * 16 ch
        int kyi = idx >> 4, ff = idx & 15;
        __half2 h = src[(size_t)kyi * 256 * 128 + ff];      // 64B chunks
        float2 v = __half22float2(h);
        sbuf[kyi * 17 + ff] = v;
    }
    __syncthreads();

    float2 x[8];
#pragma unroll
    for (int j = 0; j < 8; j++) x[j] = sbuf[(n1 + 16 * j) * 17 + f];
    __syncthreads();                               // before sbuf reuse

    float2 A[16];
    dft16_half(x, A);

    float sn, cs;
    sincosf(PI_F * (float)n1 / 128.f, &sn, &cs);
    float2 base = make_float2(cs, sn), w = make_float2(1.f, 0.f);
    float2* tp = sbuf + f * 272 + n1;
#pragma unroll
    for (int k1 = 0; k1 < 16; k1++) {
        tp[k1 * 17] = cmul(A[k1], w);
        w = cmul(w, base);
    }
    __syncthreads();

    float2 c[16];
    const float2* rp = sbuf + f * 272 + n1 * 17;
#pragma unroll
    for (int i = 0; i < 16; i++) c[i] = rp[i];
    __syncthreads();

    float2 X[16];
    dft16_full(c, X);                              // X[k2] -> y-pos n1 + 16*k2

#pragma unroll
    for (int k2 = 0; k2 < 16; k2++) sbuf[(n1 + 16 * k2) * 17 + f] = X[k2];
    __syncthreads();

    // g_feat as half2: texel (y,xcol), pair index ch
    __half2* dst = (__half2*)g_feat + (size_t)xcol * 128 + g * 16;
#pragma unroll
    for (int k = 0; k < 16; k++) {
        int idx = tid + k * 256;                   // 4096 = 256 y * 16 ch
        int y = idx >> 4, ff = idx & 15;
        float2 v = sbuf[y * 17 + ff];              // unnormalized (1/65536 deferred)
        dst[(size_t)y * 256 * 128 + ff] = __floats2half2_rn(v.x, v.y);
    }
}

// ===========================================================================
// Sampler (R9 version, natural point order — proven fastest): one warp per
// point; lane t owns feat halves [8t,8t+8); lanes 0-15 real block (cos),
// lanes 16-31 imag block (-sin), folded into __sinf via sign/offset.
// ===========================================================================
__global__ void __launch_bounds__(256)
ksample(const float* __restrict__ inputs, float* __restrict__ out,
        int ix, int iy, int is, int accum) {
    int warp = (blockIdx.x * blockDim.x + threadIdx.x) >> 5;
    int lane = threadIdx.x & 31;
    if (warp >= NPTS) return;

    float gx = __ldg(inputs + warp * 3 + ix);
    float gy = __ldg(inputs + warp * 3 + iy);
    float ic = __ldg(inputs + warp * 3 + is);

    float xx = (gx + 1.f) * 127.5f;
    float yy = (gy + 1.f) * 127.5f;
    float xf = floorf(xx), yf = floorf(yy);
    float wx = xx - xf, wy = yy - yf;
    int x0 = min(max((int)xf, 0), 255);
    int x1 = min(x0 + 1, 255);
    int y0 = min(max((int)yf, 0), 255);
    int y1 = min(y0 + 1, 255);
    __half2 w00 = __float2half2_rn((1.f - wx) * (1.f - wy));
    __half2 w01 = __float2half2_rn(wx * (1.f - wy));
    __half2 w10 = __float2half2_rn((1.f - wx) * wy);
    __half2 w11 = __float2half2_rn(wx * wy);

    int co = lane << 3;
    uint4 u00 = __ldg((const uint4*)(g_feat + ((((y0 << 8) + x0) << 8) + co)));
    uint4 u01 = __ldg((const uint4*)(g_feat + ((((y0 << 8) + x1) << 8) + co)));
    uint4 u10 = __ldg((const uint4*)(g_feat + ((((y1 << 8) + x0) << 8) + co)));
    uint4 u11 = __ldg((const uint4*)(g_feat + ((((y1 << 8) + x1) << 8) + co)));
    const __half2* h00 = (const __half2*)&u00;
    const __half2* h01 = (const __half2*)&u01;
    const __half2* h10 = (const __half2*)&u10;
    const __half2* h11 = (const __half2*)&u11;

    float F[8];
#pragma unroll
    for (int k = 0; k < 4; k++) {
        __half2 a = __hfma2(w01, h01[k], __hmul2(w00, h00[k]));
        __half2 b = __hfma2(w11, h11[k], __hmul2(w10, h10[k]));
        float2 fa = __half22float2(a);
        float2 fb = __half22float2(b);
        F[2 * k]     = fa.x + fb.x;
        F[2 * k + 1] = fa.y + fb.y;
    }

    float s = (ic + 1.f) * 127.5f;
    float a = s * (PI_F / 128.f);
    bool re = (lane < 16);
    float sa  = re ? a : -a;
    float off = re ? (PI_F * 0.5f) : 0.f;
    float val = re ? F[0] : 0.f;
#pragma unroll
    for (int r = 1; r < 8; r++) {
        float th = fmaf((float)((1 << r) - 1), sa, off);
        val = fmaf(F[r], __sinf(th), val);
    }
    val += __shfl_down_sync(0xffffffffu, val, 16);
    if (lane < 16) {
        float v = val * (1.f / 65536.f);
        float* o = out + warp * CHOUT + lane;
        if (accum) *o += v; else *o = v;
    }
}

// ---------------------------------------------------------------------------
extern "C" void kernel_launch(void* const* d_in, const int* in_sizes, int n_in,
                              void* d_out, int out_size) {
    const float* inp = (const float*)d_in[3];
    float* out = (float*)d_out;
    const int sel[3][3] = { {1, 2, 0},   // Pu
                            {0, 2, 1},   // Pv
                            {0, 1, 2} }; // Pw
    for (int p = 0; p < 3; p++) {
        const float* P = (const float*)d_in[p];
        kfftx<<<dim3(NCH / 16, 128), 256>>>(P);
        kffty<<<dim3(NCH / 16, 256), 256>>>();
        ksample<<<NPTS / 8, 256>>>(inp, out, sel[p][0], sel[p][1], sel[p][2], p > 0);
    }
}

// round 12
// speedup vs baseline: 1.9055x; 1.1095x over previous
#include <cuda_runtime.h>
#include <cuda_fp16.h>

#define RES     256
#define CHOUT   16
#define NCH     128          // CH*RR phasor channels per plane
#define NPTS    262144
#define PI_F    3.14159265358979323846f

// Scratch (device globals: allocation-free rule)
// g_mid layout: [x][ky][ch]  (x<256, ky<128, ch<128), complex fp16, 16.7 MB
__device__ __half2 g_mid[256 * 128 * NCH];
__device__ __half  g_feat[RES * RES * 2 * NCH];    // [y][x][256ch] fp16 unnormalized

__device__ __forceinline__ float2 cadd(float2 a, float2 b) { return make_float2(a.x + b.x, a.y + b.y); }
__device__ __forceinline__ float2 csub(float2 a, float2 b) { return make_float2(a.x - b.x, a.y - b.y); }
__device__ __forceinline__ float2 cmul(float2 a, float2 b) {
    return make_float2(fmaf(a.x, b.x, -a.y * b.y), fmaf(a.x, b.y, a.y * b.x));
}
__device__ __forceinline__ float2 muli(float2 a) { return make_float2(-a.y, a.x); }

// ===========================================================================
// Register DFT-16 (inverse, +i), radix-4 x radix-4, natural-order output.
// ===========================================================================
__device__ __forceinline__ float2 w16m(int k) {
    const float C1 = 0.9238795325112867f, S1 = 0.3826834323650898f;
    const float C2 = 0.7071067811865476f;
    switch (k) {
        case 0:  return make_float2( 1.f, 0.f);
        case 1:  return make_float2( C1,  S1);
        case 2:  return make_float2( C2,  C2);
        case 3:  return make_float2( S1,  C1);
        case 4:  return make_float2( 0.f, 1.f);
        case 6:  return make_float2(-C2,  C2);
        default: return make_float2(-C1, -S1);     // case 9
    }
}

__device__ __forceinline__ void dft4i(float2& x0, float2& x1, float2& x2, float2& x3) {
    float2 a = cadd(x0, x2), b = csub(x0, x2);
    float2 c = cadd(x1, x3), d = muli(csub(x1, x3));
    x0 = cadd(a, c); x1 = cadd(b, d); x2 = csub(a, c); x3 = csub(b, d);
}

__device__ __forceinline__ void dft16_tail(float2 d[16], float2 out[16]) {
#pragma unroll
    for (int m = 0; m < 4; m++) {
        float2 e0 = d[0 + 4 * m];
        float2 e1 = cmul(d[1 + 4 * m], w16m(1 * m));
        float2 e2 = cmul(d[2 + 4 * m], w16m(2 * m));
        float2 e3 = cmul(d[3 + 4 * m], w16m(3 * m));
        float2 A = cadd(e0, e2), B = csub(e0, e2);
        float2 C = cadd(e1, e3), D = muli(csub(e1, e3));
        out[m]      = cadd(A, C);
        out[m + 4]  = cadd(B, D);
        out[m + 8]  = csub(A, C);
        out[m + 12] = csub(B, D);
    }
}

__device__ __forceinline__ void dft16_full(float2 x[16], float2 out[16]) {
#pragma unroll
    for (int a = 0; a < 4; a++) dft4i(x[a], x[a + 4], x[a + 8], x[a + 12]);
    dft16_tail(x, out);
}

__device__ __forceinline__ void dft16_half(const float2 x[8], float2 out[16]) {
    float2 d[16];
#pragma unroll
    for (int a = 0; a < 4; a++) {
        float2 u = x[a], v = x[a + 4];
        float2 iv = muli(v);
        d[a]      = cadd(u, v);
        d[a + 4]  = cadd(u, iv);
        d[a + 8]  = csub(u, v);
        d[a + 12] = csub(u, iv);
    }
    dft16_tail(d, out);
}

// ===========================================================================
// FFT kernels: 16 threads per 256-pt IFFT, 16 FFTs/block, ONE smem round.
// Phase-1 roles pick input coalescing; phase-2 roles (f2 = tid&15) make the
// output channel-fastest so results write straight to gmem (64B chunks).
// Working buffer stride 273 float2: banks (f*546 + k1*34 + 2*n1) mod 32
// distinct within each half-warp for all four access patterns.
// ===========================================================================

// Kernel A: x-direction IFFT for the 128 nonzero rows. grid=(NCH/16, 128).
__global__ void __launch_bounds__(256) kfftx(const float* __restrict__ P) {
    __shared__ float2 sbuf[16 * 273];              // 34.9 KB
    int tid = threadIdx.x, g = blockIdx.x, ky = blockIdx.y;

    // --- phase 1: n1-fastest (coalesced 128B row reads) ---
    int n1 = tid & 15, f = tid >> 4;
    const float2* row = (const float2*)P + ((size_t)(g * 16 + f) * 256 + ky) * 256;
    float2 x[8];
#pragma unroll
    for (int j = 0; j < 8; j++) x[j] = row[n1 + 16 * j];

    float2 A[16];
    dft16_half(x, A);

    float sn, cs;
    sincosf(PI_F * (float)n1 / 128.f, &sn, &cs);   // exp(+i*2pi*n1/256)
    float2 base = make_float2(cs, sn), w = make_float2(1.f, 0.f);
    float2* tp = sbuf + f * 273 + n1;
#pragma unroll
    for (int k1 = 0; k1 < 16; k1++) {
        tp[k1 * 17] = cmul(A[k1], w);
        w = cmul(w, base);
    }
    __syncthreads();

    // --- phase 2: f2-fastest (channel-contiguous output) ---
    int f2 = tid & 15, t2 = tid >> 4;
    float2 c[16];
    const float2* rp = sbuf + f2 * 273 + t2 * 17;
#pragma unroll
    for (int i = 0; i < 16; i++) c[i] = rp[i];

    float2 X[16];
    dft16_full(c, X);                              // X[k2] -> x-pos t2 + 16*k2

    // direct write, layout [x][ky][ch]; 16 consecutive ch = 64B per half-warp
    __half2* dst = g_mid + ((size_t)t2 * 128 + ky) * 128 + g * 16 + f2;
#pragma unroll
    for (int k2 = 0; k2 < 16; k2++)
        dst[(size_t)(16 * k2) * 128 * 128] = __floats2half2_rn(X[k2].x, X[k2].y);
}

// Kernel B: y-direction IFFT (ky>=128 zero), fp16 texel-major output.
// grid=(NCH/16, 256).
__global__ void __launch_bounds__(256) kffty() {
    __shared__ float2 sbuf[16 * 273];
    int tid = threadIdx.x, g = blockIdx.x, xcol = blockIdx.y;

    // --- phase 1: f-fastest (channel-contiguous input, 64B chunks) ---
    int f = tid & 15, n1 = tid >> 4;
    const __half2* src = g_mid + (size_t)xcol * 128 * 128 + g * 16 + f;
    float2 x[8];
#pragma unroll
    for (int j = 0; j < 8; j++)
        x[j] = __half22float2(src[(size_t)(n1 + 16 * j) * 128]);

    float2 A[16];
    dft16_half(x, A);

    float sn, cs;
    sincosf(PI_F * (float)n1 / 128.f, &sn, &cs);
    float2 base = make_float2(cs, sn), w = make_float2(1.f, 0.f);
    float2* tp = sbuf + f * 273 + n1;
#pragma unroll
    for (int k1 = 0; k1 < 16; k1++) {
        tp[k1 * 17] = cmul(A[k1], w);
        w = cmul(w, base);
    }
    __syncthreads();

    // --- phase 2: f2-fastest (channel-contiguous feat output) ---
    int f2 = tid & 15, t2 = tid >> 4;
    float2 c[16];
    const float2* rp = sbuf + f2 * 273 + t2 * 17;
#pragma unroll
    for (int i = 0; i < 16; i++) c[i] = rp[i];

    float2 X[16];
    dft16_full(c, X);                              // X[k2] -> y-pos t2 + 16*k2

    // g_feat as half2: ((y*256 + xcol)*128 + ch); unnormalized (1/65536 deferred)
    __half2* dst = (__half2*)g_feat + ((size_t)t2 * 256 + xcol) * 128 + g * 16 + f2;
#pragma unroll
    for (int k2 = 0; k2 < 16; k2++)
        dst[(size_t)(16 * k2) * 256 * 128] = __floats2half2_rn(X[k2].x, X[k2].y);
}

// ===========================================================================
// Sampler (R9/R11 version, natural point order — proven fastest): one warp
// per point; lane t owns feat halves [8t,8t+8); lanes 0-15 real block (cos),
// lanes 16-31 imag block (-sin), folded into __sinf via sign/offset.
// ===========================================================================
__global__ void __launch_bounds__(256)
ksample(const float* __restrict__ inputs, float* __restrict__ out,
        int ix, int iy, int is, int accum) {
    int warp = (blockIdx.x * blockDim.x + threadIdx.x) >> 5;
    int lane = threadIdx.x & 31;
    if (warp >= NPTS) return;

    float gx = __ldg(inputs + warp * 3 + ix);
    float gy = __ldg(inputs + warp * 3 + iy);
    float ic = __ldg(inputs + warp * 3 + is);

    float xx = (gx + 1.f) * 127.5f;
    float yy = (gy + 1.f) * 127.5f;
    float xf = floorf(xx), yf = floorf(yy);
    float wx = xx - xf, wy = yy - yf;
    int x0 = min(max((int)xf, 0), 255);
    int x1 = min(x0 + 1, 255);
    int y0 = min(max((int)yf, 0), 255);
    int y1 = min(y0 + 1, 255);
    __half2 w00 = __float2half2_rn((1.f - wx) * (1.f - wy));
    __half2 w01 = __float2half2_rn(wx * (1.f - wy));
    __half2 w10 = __float2half2_rn((1.f - wx) * wy);
    __half2 w11 = __float2half2_rn(wx * wy);

    int co = lane << 3;
    uint4 u00 = __ldg((const uint4*)(g_feat + ((((y0 << 8) + x0) << 8) + co)));
    uint4 u01 = __ldg((const uint4*)(g_feat + ((((y0 << 8) + x1) << 8) + co)));
    uint4 u10 = __ldg((const uint4*)(g_feat + ((((y1 << 8) + x0) << 8) + co)));
    uint4 u11 = __ldg((const uint4*)(g_feat + ((((y1 << 8) + x1) << 8) + co)));
    const __half2* h00 = (const __half2*)&u00;
    const __half2* h01 = (const __half2*)&u01;
    const __half2* h10 = (const __half2*)&u10;
    const __half2* h11 = (const __half2*)&u11;

    float F[8];
#pragma unroll
    for (int k = 0; k < 4; k++) {
        __half2 a = __hfma2(w01, h01[k], __hmul2(w00, h00[k]));
        __half2 b = __hfma2(w11, h11[k], __hmul2(w10, h10[k]));
        float2 fa = __half22float2(a);
        float2 fb = __half22float2(b);
        F[2 * k]     = fa.x + fb.x;
        F[2 * k + 1] = fa.y + fb.y;
    }

    float s = (ic + 1.f) * 127.5f;
    float a = s * (PI_F / 128.f);
    bool re = (lane < 16);
    float sa  = re ? a : -a;
    float off = re ? (PI_F * 0.5f) : 0.f;
    float val = re ? F[0] : 0.f;
#pragma unroll
    for (int r = 1; r < 8; r++) {
        float th = fmaf((float)((1 << r) - 1), sa, off);
        val = fmaf(F[r], __sinf(th), val);
    }
    val += __shfl_down_sync(0xffffffffu, val, 16);
    if (lane < 16) {
        float v = val * (1.f / 65536.f);
        float* o = out + warp * CHOUT + lane;
        if (accum) *o += v; else *o = v;
    }
}

// ---------------------------------------------------------------------------
extern "C" void kernel_launch(void* const* d_in, const int* in_sizes, int n_in,
                              void* d_out, int out_size) {
    const float* inp = (const float*)d_in[3];
    float* out = (float*)d_out;
    const int sel[3][3] = { {1, 2, 0},   // Pu
                            {0, 2, 1},   // Pv
                            {0, 1, 2} }; // Pw
    for (int p = 0; p < 3; p++) {
        const float* P = (const float*)d_in[p];
        kfftx<<<dim3(NCH / 16, 128), 256>>>(P);
        kffty<<<dim3(NCH / 16, 256), 256>>>();
        ksample<<<NPTS / 8, 256>>>(inp, out, sel[p][0], sel[p][1], sel[p][2], p > 0);
    }
}